// round 9
// baseline (speedup 1.0000x reference)
#include <cuda_runtime.h>
#include <math.h>
#include <stdint.h>

// Problem constants
#define MTOK   32768
#define DDIM   2048
#define NEXP   64
#define TOPK   8
#define NCOLS  128            // router(64) || noise(64)

// Tiling: 128 threads, per-thread 8 tokens x 8 cols (token-dup x, natural w pairs)
#define BM      64
#define DK      32
#define NTHREADS 128          // tx = tid&15 (col group), ty = tid>>4 (token octet)
#define NKB     (DDIM / DK)   // 64 chunks

// smem: two buffers [xs | ws]; epilogue ls aliases buffer region.
#define XROW      132                         // xs row stride (floats): dup pairs, 16B-aligned
#define XS_BYTES  (DK * XROW * 4)             // 16896
#define WS_BYTES  (DK * NCOLS * 4)            // 16384
#define BUF_BYTES (XS_BYTES + WS_BYTES)       // 33280
#define SMEM_BYTES (2 * BUF_BYTES)            // 66560
#define LSTRIDE   133                         // 64*133*4 = 34048 <= SMEM_BYTES

typedef unsigned long long ull;

__device__ __forceinline__ void fma2(ull &acc, ull a, ull b) {
    asm("fma.rn.f32x2 %0, %1, %2, %0;" : "+l"(acc) : "l"(a), "l"(b));
}
__device__ __forceinline__ void add2(ull &acc, ull a) {
    asm("add.rn.f32x2 %0, %0, %1;" : "+l"(acc) : "l"(a));
}
__device__ __forceinline__ float lo2(ull v) { return __uint_as_float((unsigned)v); }
__device__ __forceinline__ float hi2(ull v) { return __uint_as_float((unsigned)(v >> 32)); }

__device__ __forceinline__ void cp16(uint32_t dst_smem, const void* src) {
    asm volatile("cp.async.ca.shared.global [%0], [%1], 16;\n" :: "r"(dst_smem), "l"(src));
}
__device__ __forceinline__ void cp_commit() { asm volatile("cp.async.commit_group;\n"); }
__device__ __forceinline__ void cp_wait()   { asm volatile("cp.async.wait_group 0;\n" ::: "memory"); }

__global__ __launch_bounds__(NTHREADS) void router_kernel(
    const float* __restrict__ x,     const float* __restrict__ eps,
    const float* __restrict__ wr,    const float* __restrict__ br,
    const float* __restrict__ wn,    const float* __restrict__ bn,
    const float* __restrict__ wskip, const float* __restrict__ bskip,
    float* __restrict__ out_router, float* __restrict__ out_idx,
    float* __restrict__ out_skip)
{
    extern __shared__ __align__(16) unsigned char smem[];
    float (*ls)[LSTRIDE] = (float(*)[LSTRIDE])smem;   // epilogue only (aliases buffers)

    uint32_t sbase;
    asm("{ .reg .u64 t; cvta.to.shared.u64 t, %1; cvt.u32.u64 %0, t; }"
        : "=r"(sbase) : "l"(smem));

    const int tid  = threadIdx.x;
    const int tx   = tid & 15;       // cols {4tx+c, 4tx+64+c}, c=0..3
    const int ty   = tid >> 4;       // tokens 8ty .. 8ty+7
    const int ptok = tid >> 1;       // prefetch token 0..63
    const int pq   = (tid & 1) * 4;  // prefetch d-quad base (quads pq..pq+3)
    const int m0   = blockIdx.x * BM;

    // outer accumulators: acc[t][p] = token (8ty+t) x col-pair p
    //   p -> cols (4tx + 64*(p>>1) + 2*(p&1)) + {0,1}
    ull acc[8][4];
    #pragma unroll
    for (int t = 0; t < 8; t++)
        #pragma unroll
        for (int p = 0; p < 4; p++) acc[t][p] = 0ull;
    float sk = 0.f;                  // skip partial: token ptok, d-quads pq..pq+3 of each chunk

    // ================= prologue: stage chunk 0 into buffer 0 =================
    float4 xr[4];
    {
        #pragma unroll
        for (int i = 0; i < 8; i++) {       // w panel: 1024 float4s (natural layout)
            int fid = tid + i * NTHREADS;
            int d   = fid >> 5;
            int col = (fid & 31) * 4;
            const float* src = (col < 64) ? (wr + (size_t)d * NEXP + col)
                                          : (wn + (size_t)d * NEXP + (col - 64));
            cp16(sbase + XS_BYTES + (uint32_t)(d * NCOLS + col) * 4, src);
        }
        cp_commit();
        #pragma unroll
        for (int i = 0; i < 4; i++) {
            int q = pq + i;
            xr[i] = *(const float4*)(x + (size_t)(m0 + ptok) * DDIM + q * 4);
            float4 w4 = *(const float4*)(wskip + q * 4);
            sk = fmaf(xr[i].x, w4.x, fmaf(xr[i].y, w4.y,
                 fmaf(xr[i].z, w4.z, fmaf(xr[i].w, w4.w, sk))));
        }
        float* xs0 = (float*)smem;
        #pragma unroll
        for (int i = 0; i < 4; i++) {
            int d0 = (pq + i) * 4;
            *(float2*)&xs0[(d0 + 0) * XROW + 2 * ptok] = make_float2(xr[i].x, xr[i].x);
            *(float2*)&xs0[(d0 + 1) * XROW + 2 * ptok] = make_float2(xr[i].y, xr[i].y);
            *(float2*)&xs0[(d0 + 2) * XROW + 2 * ptok] = make_float2(xr[i].z, xr[i].z);
            *(float2*)&xs0[(d0 + 3) * XROW + 2 * ptok] = make_float2(xr[i].w, xr[i].w);
        }
        cp_wait();
    }
    __syncthreads();

    // ================= main loop =================
    for (int kb = 0; kb < NKB; kb++) {
        const int cur = kb & 1;
        const float* xsb = (const float*)(smem + (size_t)cur * BUF_BYTES);
        const float* wsb = (const float*)(smem + (size_t)cur * BUF_BYTES + XS_BYTES);

        // ---- prefetch chunk kb+1 ----
        if (kb < NKB - 1) {
            const int k0 = (kb + 1) * DK;
            const uint32_t nxtoff = (uint32_t)(cur ^ 1) * BUF_BYTES;
            #pragma unroll
            for (int i = 0; i < 8; i++) {
                int fid = tid + i * NTHREADS;
                int d   = fid >> 5;
                int col = (fid & 31) * 4;
                const float* src = (col < 64) ? (wr + (size_t)(k0 + d) * NEXP + col)
                                              : (wn + (size_t)(k0 + d) * NEXP + (col - 64));
                cp16(sbase + nxtoff + XS_BYTES + (uint32_t)(d * NCOLS + col) * 4, src);
            }
            cp_commit();
            #pragma unroll
            for (int i = 0; i < 4; i++) {
                int q = pq + i;
                xr[i] = *(const float4*)(x + (size_t)(m0 + ptok) * DDIM + k0 + q * 4);
                float4 w4 = *(const float4*)(wskip + k0 + q * 4);
                sk = fmaf(xr[i].x, w4.x, fmaf(xr[i].y, w4.y,
                     fmaf(xr[i].z, w4.z, fmaf(xr[i].w, w4.w, sk))));
            }
        }

        // ---- FFMA2 mainloop: dup'd x tokens, natural w col-pairs, zero MOVs ----
        ull inner[8][4];
        #pragma unroll
        for (int t = 0; t < 8; t++)
            #pragma unroll
            for (int p = 0; p < 4; p++) inner[t][p] = 0ull;

        #pragma unroll
        for (int d = 0; d < DK; d++) {
            // 8 dup'd tokens: 4 x LDS.128 (broadcast across tx)
            ulonglong2 xv0 = *(const ulonglong2*)(xsb + d * XROW + 16 * ty);
            ulonglong2 xv1 = *(const ulonglong2*)(xsb + d * XROW + 16 * ty + 4);
            ulonglong2 xv2 = *(const ulonglong2*)(xsb + d * XROW + 16 * ty + 8);
            ulonglong2 xv3 = *(const ulonglong2*)(xsb + d * XROW + 16 * ty + 12);
            // 8 cols as 4 natural pairs: 2 x LDS.128
            ulonglong2 wA = *(const ulonglong2*)(wsb + d * NCOLS + 4 * tx);       // pairs p0,p1
            ulonglong2 wB = *(const ulonglong2*)(wsb + d * NCOLS + 4 * tx + 64);  // pairs p2,p3
            ull xd[8] = {xv0.x, xv0.y, xv1.x, xv1.y, xv2.x, xv2.y, xv3.x, xv3.y};
            #pragma unroll
            for (int t = 0; t < 8; t++) {
                fma2(inner[t][0], xd[t], wA.x);
                fma2(inner[t][1], xd[t], wA.y);
                fma2(inner[t][2], xd[t], wB.x);
                fma2(inner[t][3], xd[t], wB.y);
            }
        }
        #pragma unroll
        for (int t = 0; t < 8; t++)
            #pragma unroll
            for (int p = 0; p < 4; p++) add2(acc[t][p], inner[t][p]);

        // ---- store prefetched x (dup'd) into next buffer, drain cp.async ----
        if (kb < NKB - 1) {
            float* xsn = (float*)(smem + (size_t)(cur ^ 1) * BUF_BYTES);
            #pragma unroll
            for (int i = 0; i < 4; i++) {
                int d0 = (pq + i) * 4;
                *(float2*)&xsn[(d0 + 0) * XROW + 2 * ptok] = make_float2(xr[i].x, xr[i].x);
                *(float2*)&xsn[(d0 + 1) * XROW + 2 * ptok] = make_float2(xr[i].y, xr[i].y);
                *(float2*)&xsn[(d0 + 2) * XROW + 2 * ptok] = make_float2(xr[i].z, xr[i].z);
                *(float2*)&xsn[(d0 + 3) * XROW + 2 * ptok] = make_float2(xr[i].w, xr[i].w);
            }
            cp_wait();
        }
        __syncthreads();
    }

    // ---- stage logits (+bias) into ls (aliases buffers; all reads done) ----
    #pragma unroll
    for (int t = 0; t < 8; t++) {
        int tok = 8 * ty + t;
        #pragma unroll
        for (int p = 0; p < 4; p++) {
            int c0 = 4 * tx + 64 * (p >> 1) + 2 * (p & 1);
            float b0 = (c0 < 64) ? __ldg(br + c0) : __ldg(bn + c0 - 64);
            float b1 = (c0 + 1 < 64) ? __ldg(br + c0 + 1) : __ldg(bn + c0 + 1 - 64);
            ls[tok][c0]     = __fadd_rn(lo2(acc[t][p]), b0);
            ls[tok][c0 + 1] = __fadd_rn(hi2(acc[t][p]), b1);
        }
    }
    // ---- skip-dot: combine the two half-token partials (lanes tid, tid^1) ----
    {
        float sko = __shfl_xor_sync(0xffffffffu, sk, 1);
        if ((tid & 1) == 0)
            ls[ptok][128] = __fadd_rn(sk + sko, __ldg(bskip));
    }
    __syncthreads();

    // ---- noisy logits: 4096 (tok,e) pairs over 128 threads ----
    #pragma unroll
    for (int i = 0; i < 32; i++) {
        int fid = tid + i * NTHREADS;
        int tok = fid >> 6;
        int e   = fid & 63;
        float  lg = ls[tok][e];
        float  no = ls[tok][64 + e];
        double nd = (double)no;
        float  sp = (float)(fmax(nd, 0.0) + log1p(exp(-fabs(nd))));
        float  ev = __ldg(eps + (size_t)(m0 + tok) * NEXP + e);
        ls[tok][e] = __fadd_rn(lg, __fmul_rn(ev, sp));
    }
    __syncthreads();

    // ---- top-8 + softmax (one thread per token) ----
    if (tid < BM) {
        const int tok = tid;
        float vals[TOPK]; int idxs[TOPK];
        for (int k = 0; k < TOPK; k++) {
            float best = -3.402823466e38f; int bi = 0;
            for (int e = 0; e < NEXP; e++) {
                float v = ls[tok][e];
                if (v > best) { best = v; bi = e; }
            }
            vals[k] = best; idxs[k] = bi;
            ls[tok][bi] = -3.402823466e38f;
        }
        float mx = vals[0];
        float gsv[TOPK]; float s = 0.f;
        #pragma unroll
        for (int k = 0; k < TOPK; k++) { gsv[k] = expf(vals[k] - mx); s += gsv[k]; }
        float inv = 1.f / s;
        for (int e = 0; e < NEXP; e++) ls[tok][e] = 0.f;
        #pragma unroll
        for (int k = 0; k < TOPK; k++) ls[tok][idxs[k]] = gsv[k] * inv;
        #pragma unroll
        for (int k = 0; k < TOPK; k++) ls[tok][64 + k] = (float)idxs[k];
    }
    __syncthreads();

    // ---- cooperative coalesced stores ----
    #pragma unroll
    for (int i = 0; i < 32; i++) {
        int fid = tid + i * NTHREADS;
        int tok = fid >> 6;
        int e   = fid & 63;
        out_router[(size_t)(m0 + tok) * NEXP + e] = ls[tok][e];
    }
    #pragma unroll
    for (int i = 0; i < 4; i++) {
        int fid = tid + i * NTHREADS;
        int tok = fid >> 3;
        int k   = fid & 7;
        out_idx[(size_t)(m0 + tok) * TOPK + k] = ls[tok][64 + k];
    }
    if (tid < BM) {
        float z = ls[tid][128];
        out_skip[m0 + tid] = 1.f / (1.f + expf(-z));
    }
}

extern "C" void kernel_launch(void* const* d_in, const int* in_sizes, int n_in,
                              void* d_out, int out_size)
{
    const float* x     = (const float*)d_in[0];
    const float* eps   = (const float*)d_in[1];
    const float* wr    = (const float*)d_in[2];
    const float* br    = (const float*)d_in[3];
    const float* wn    = (const float*)d_in[4];
    const float* bn    = (const float*)d_in[5];
    const float* wskip = (const float*)d_in[6];
    const float* bskip = (const float*)d_in[7];

    float* out        = (float*)d_out;
    float* out_router = out;                                   // [32768, 64]
    float* out_idx    = out + (size_t)MTOK * NEXP;             // [32768, 8] as float
    float* out_skip   = out_idx + (size_t)MTOK * TOPK;         // [32768, 1]

    cudaFuncSetAttribute(router_kernel, cudaFuncAttributeMaxDynamicSharedMemorySize, SMEM_BYTES);
    router_kernel<<<MTOK / BM, NTHREADS, SMEM_BYTES>>>(x, eps, wr, br, wn, bn, wskip, bskip,
                                                       out_router, out_idx, out_skip);
}